// round 6
// baseline (speedup 1.0000x reference)
#include <cuda_runtime.h>

#define C      128
#define PP     4
#define NMAX   200000
#define EMAX   600000
#define ASTRIDE 132   // 128 + 4 pad: keeps 16B alignment, cuts STS conflicts 8-way -> 4-way

// ---------------- persistent device scratch (no allocations allowed) -------
__device__ float g_xcur[(size_t)NMAX * C];
__device__ float g_h1  [(size_t)NMAX * C];
__device__ float g_agg [(size_t)NMAX * C];
__device__ int   g_cnt     [PP * NMAX];
__device__ int   g_rowptr  [PP * NMAX + 1];
__device__ int   g_cursor  [PP * NMAX];
__device__ int   g_involved[PP * NMAX];
__device__ int   g_list    [PP * NMAX];
__device__ int   g_srcs    [EMAX];
__device__ unsigned char g_eper[EMAX];
__device__ int   g_bsums   [1024];
__device__ int   g_ninv    [PP];

// ---------------- init / zero ------------------------------------------------
__global__ void k_zero(int n4) {
    int i = blockIdx.x * blockDim.x + threadIdx.x;
    if (i < n4) { g_cnt[i] = 0; g_involved[i] = 0; }
    if (i < PP) g_ninv[i] = 0;
}

__global__ void k_copy_x(const float4* __restrict__ x, int nv) {
    int i = blockIdx.x * blockDim.x + threadIdx.x;
    if (i < nv) reinterpret_cast<float4*>(g_xcur)[i] = x[i];
}

// ---------------- edge pass: per-edge period, CSR counts, involved marks ----
__global__ void k_edge(const int* __restrict__ ei, const int* __restrict__ nt,
                       const int* __restrict__ minT, const int* __restrict__ up,
                       int E_, int n) {
    int e = blockIdx.x * blockDim.x + threadIdx.x;
    if (e >= E_) return;
    int s = __ldg(ei + e), d = __ldg(ei + E_ + e);
    int intro = max(__ldg(nt + s), __ldg(nt + d));
    int p = (intro - minT[0]) / up[0];
    p = min(max(p, 0), PP - 1);
    g_eper[e] = (unsigned char)p;
    atomicAdd(&g_cnt[p * n + d], 1);
    g_involved[p * n + s] = 1;
    g_involved[p * n + d] = 1;
}

// ---------------- exclusive scan over g_cnt (3-phase) -----------------------
__global__ void k_scan1(int n4) {
    __shared__ int sh[256];
    int t = threadIdx.x;
    int base = blockIdx.x * 1024 + t * 4;
    int v0 = (base + 0 < n4) ? g_cnt[base + 0] : 0;
    int v1 = (base + 1 < n4) ? g_cnt[base + 1] : 0;
    int v2 = (base + 2 < n4) ? g_cnt[base + 2] : 0;
    int v3 = (base + 3 < n4) ? g_cnt[base + 3] : 0;
    int ts = v0 + v1 + v2 + v3;
    sh[t] = ts;
    __syncthreads();
    for (int off = 1; off < 256; off <<= 1) {
        int y = (t >= off) ? sh[t - off] : 0;
        __syncthreads();
        sh[t] += y;
        __syncthreads();
    }
    int run = sh[t] - ts;  // exclusive prefix for this thread's 4 elems
    if (base + 0 < n4) g_rowptr[base + 0] = run;  run += v0;
    if (base + 1 < n4) g_rowptr[base + 1] = run;  run += v1;
    if (base + 2 < n4) g_rowptr[base + 2] = run;  run += v2;
    if (base + 3 < n4) g_rowptr[base + 3] = run;
    if (t == 255) g_bsums[blockIdx.x] = sh[255];
}

__global__ void k_scan2(int nb) {
    __shared__ int sh[1024];
    int t = threadIdx.x;
    int v = (t < nb) ? g_bsums[t] : 0;
    sh[t] = v;
    __syncthreads();
    for (int off = 1; off < 1024; off <<= 1) {
        int y = (t >= off) ? sh[t - off] : 0;
        __syncthreads();
        sh[t] += y;
        __syncthreads();
    }
    if (t < nb) g_bsums[t] = sh[t] - v;  // exclusive
}

__global__ void k_scan3(int n4, int Etot) {
    int i = blockIdx.x * blockDim.x + threadIdx.x;
    if (i < n4) {
        int r = g_rowptr[i] + g_bsums[i >> 10];
        g_rowptr[i] = r;
        g_cursor[i] = r;
    }
    if (i == 0) g_rowptr[n4] = Etot;
}

// ---------------- CSR fill (uses cached per-edge period) --------------------
__global__ void k_scatter(const int* __restrict__ ei, int E_, int n) {
    int e = blockIdx.x * blockDim.x + threadIdx.x;
    if (e >= E_) return;
    int s = __ldg(ei + e), d = __ldg(ei + E_ + e);
    int p = (int)g_eper[e];
    int pos = atomicAdd(&g_cursor[p * n + d], 1);
    g_srcs[pos] = s;
}

// ---------------- involved-node compaction (warp-aggregated) ----------------
__global__ void k_compact(int n, int n4) {
    int i = blockIdx.x * blockDim.x + threadIdx.x;
    int flag = (i < n4) ? g_involved[i] : 0;
    unsigned m = __ballot_sync(0xffffffffu, flag != 0);
    if (!flag) return;
    int lane = threadIdx.x & 31;
    int p = i / n;                       // warp never straddles p (n % 32 == 0)
    int leader = __ffs(m) - 1;
    int base = 0;
    if (lane == leader) base = atomicAdd(&g_ninv[p], __popc(m));
    base = __shfl_sync(m, base, leader);
    int off = __popc(m & ((1u << lane) - 1u));
    g_list[p * n + base + off] = i - p * n;
}

// ---------------- mean-aggregation gather (1 warp per involved node) --------
// MLP=2: two edges in flight per iteration to overlap gather latency.
__global__ void k_gather(int p, int n, int layer) {
    int gw   = (blockIdx.x * blockDim.x + threadIdx.x) >> 5;
    int lane = threadIdx.x & 31;
    if (gw >= g_ninv[p]) return;
    const float* hin = (layer == 0) ? g_xcur : g_h1;
    int node = g_list[p * n + gw];
    int b0 = p * n + node;
    int s = g_rowptr[b0], e2 = g_rowptr[b0 + 1];
    float4 acc = make_float4(0.f, 0.f, 0.f, 0.f);
    int j = s;
    for (; j + 1 < e2; j += 2) {
        int src0 = g_srcs[j], src1 = g_srcs[j + 1];
        float4 v0 = *reinterpret_cast<const float4*>(hin + (size_t)src0 * C + lane * 4);
        float4 v1 = *reinterpret_cast<const float4*>(hin + (size_t)src1 * C + lane * 4);
        acc.x += v0.x + v1.x; acc.y += v0.y + v1.y;
        acc.z += v0.z + v1.z; acc.w += v0.w + v1.w;
    }
    if (j < e2) {
        int src = g_srcs[j];
        float4 v = *reinterpret_cast<const float4*>(hin + (size_t)src * C + lane * 4);
        acc.x += v.x; acc.y += v.y; acc.z += v.z; acc.w += v.w;
    }
    float inv = (e2 > s) ? 1.0f / (float)(e2 - s) : 1.0f;
    acc.x *= inv; acc.y *= inv; acc.z *= inv; acc.w *= inv;
    *reinterpret_cast<float4*>(g_agg + (size_t)node * C + lane * 4) = acc;
}

// ---------------- fused GEMM: h@Wr + agg@Wn + bias -> LN (-> ReLU) ----------
// Rows = involved nodes only. K = 256 (two halves), BN = C = 128, BM = 128.
// Software pipeline: register-prefetch tile kt+1 while computing tile kt.
__global__ void __launch_bounds__(256)
k_gemm(const float* __restrict__ wr_all, const float* __restrict__ wn_all,
       const float* __restrict__ bias_all, const float* __restrict__ lng_all,
       const float* __restrict__ lnb_all, int p, int n, int layer) {
    __shared__ __align__(16) float As[32 * ASTRIDE];
    __shared__ __align__(16) float Bs[32 * 128];
    __shared__ int ls[128];

    int nInv = g_ninv[p];
    int rowbase = blockIdx.x * 128;
    if (rowbase >= nInv) return;

    const float* hin  = (layer == 0) ? g_xcur : g_h1;
    const float* wr   = wr_all   + (size_t)layer * C * C;
    const float* wn   = wn_all   + (size_t)layer * C * C;
    const float* bias = bias_all + layer * C;
    const float* lng  = lng_all  + layer * C;
    const float* lnb  = lnb_all  + layer * C;

    int tid = threadIdx.x;
    if (tid < 128) {
        int idx = rowbase + tid;
        ls[tid] = (idx < nInv) ? g_list[p * n + idx] : g_list[p * n];  // dummy = first
    }
    __syncthreads();

    int tx = tid & 15, ty = tid >> 4;
    float acc[8][8];
#pragma unroll
    for (int i = 0; i < 8; i++)
#pragma unroll
        for (int j = 0; j < 8; j++) acc[i][j] = 0.f;

    float4 pa[4], pb[4];

    // ---- preload tile 0 into registers ----
    {
        const float* Asrc = hin;          // kt = 0
        const float* Bsrc = wr;
#pragma unroll
        for (int i = 0; i < 4; i++) {
            int id = tid + i * 256;
            int row = id >> 3, kv = id & 7;
            pa[i] = *reinterpret_cast<const float4*>(Asrc + (size_t)ls[row] * C + kv * 4);
        }
#pragma unroll
        for (int i = 0; i < 4; i++) {
            int id = tid + i * 256;
            int k = id >> 5, nv = id & 31;
            pb[i] = *reinterpret_cast<const float4*>(Bsrc + (size_t)k * C + nv * 4);
        }
    }

#pragma unroll 1
    for (int kt = 0; kt < 8; kt++) {
        // ---- commit prefetched tile kt to smem ----
#pragma unroll
        for (int i = 0; i < 4; i++) {
            int id = tid + i * 256;
            int row = id >> 3, kv = id & 7;
            As[(kv * 4 + 0) * ASTRIDE + row] = pa[i].x;
            As[(kv * 4 + 1) * ASTRIDE + row] = pa[i].y;
            As[(kv * 4 + 2) * ASTRIDE + row] = pa[i].z;
            As[(kv * 4 + 3) * ASTRIDE + row] = pa[i].w;
        }
#pragma unroll
        for (int i = 0; i < 4; i++) {
            int id = tid + i * 256;
            int k = id >> 5, nv = id & 31;
            *reinterpret_cast<float4*>(Bs + k * 128 + nv * 4) = pb[i];
        }
        __syncthreads();

        // ---- issue loads for tile kt+1 (overlapped with compute below) ----
        if (kt < 7) {
            int kn = kt + 1;
            const float* Asrc = (kn < 4) ? (hin + kn * 32) : (g_agg + (kn - 4) * 32);
            const float* Bsrc = (kn < 4) ? (wr + (size_t)kn * 32 * C)
                                         : (wn + (size_t)(kn - 4) * 32 * C);
#pragma unroll
            for (int i = 0; i < 4; i++) {
                int id = tid + i * 256;
                int row = id >> 3, kv = id & 7;
                pa[i] = *reinterpret_cast<const float4*>(Asrc + (size_t)ls[row] * C + kv * 4);
            }
#pragma unroll
            for (int i = 0; i < 4; i++) {
                int id = tid + i * 256;
                int k = id >> 5, nv = id & 31;
                pb[i] = *reinterpret_cast<const float4*>(Bsrc + (size_t)k * C + nv * 4);
            }
        }

        // ---- compute tile kt from smem ----
#pragma unroll
        for (int kk = 0; kk < 32; kk++) {
            float4 a0 = *reinterpret_cast<float4*>(As + kk * ASTRIDE + ty * 8);
            float4 a1 = *reinterpret_cast<float4*>(As + kk * ASTRIDE + ty * 8 + 4);
            float4 b0 = *reinterpret_cast<float4*>(Bs + kk * 128 + tx * 8);
            float4 b1 = *reinterpret_cast<float4*>(Bs + kk * 128 + tx * 8 + 4);
            float a[8] = {a0.x, a0.y, a0.z, a0.w, a1.x, a1.y, a1.z, a1.w};
            float b[8] = {b0.x, b0.y, b0.z, b0.w, b1.x, b1.y, b1.z, b1.w};
#pragma unroll
            for (int i = 0; i < 8; i++)
#pragma unroll
                for (int j = 0; j < 8; j++) acc[i][j] += a[i] * b[j];
        }
        __syncthreads();
    }

    // epilogue: +bias, LayerNorm across the 128 cols of each row, (+ReLU)
    float bcol[8], gcol[8], obcol[8];
#pragma unroll
    for (int j = 0; j < 8; j++) {
        int col = tx * 8 + j;
        bcol[j] = bias[col]; gcol[j] = lng[col]; obcol[j] = lnb[col];
    }
#pragma unroll
    for (int i = 0; i < 8; i++) {
        float s = 0.f, q = 0.f;
#pragma unroll
        for (int j = 0; j < 8; j++) {
            acc[i][j] += bcol[j];
            s += acc[i][j];
            q += acc[i][j] * acc[i][j];
        }
#pragma unroll
        for (int o = 1; o < 16; o <<= 1) {
            s += __shfl_xor_sync(0xffffffffu, s, o);
            q += __shfl_xor_sync(0xffffffffu, q, o);
        }
        float mu  = s * (1.0f / 128.0f);
        float var = q * (1.0f / 128.0f) - mu * mu;
        float rst = rsqrtf(var + 1e-5f);
        int ridx = rowbase + ty * 8 + i;
        bool valid = ridx < nInv;
        int node = ls[ty * 8 + i];
#pragma unroll
        for (int j = 0; j < 8; j++) {
            float v = (acc[i][j] - mu) * rst * gcol[j] + obcol[j];
            if (layer == 0) v = fmaxf(v, 0.f);
            if (valid) {
                size_t o2 = (size_t)node * C + tx * 8 + j;
                if (layer == 0) g_h1[o2] = v;
                else            g_xcur[o2] += v;
            }
        }
    }
}

// ---------------- head: out[i] = x_cur[i,:] . head_w + head_b ---------------
__global__ void k_head(const float* __restrict__ hw, const float* __restrict__ hb,
                       float* __restrict__ out, int rows) {
    int gw   = (blockIdx.x * blockDim.x + threadIdx.x) >> 5;
    int lane = threadIdx.x & 31;
    if (gw >= rows) return;
    const float* xr = g_xcur + (size_t)gw * C;
    float s = 0.f;
#pragma unroll
    for (int c = lane; c < C; c += 32) s += xr[c] * __ldg(hw + c);
#pragma unroll
    for (int o = 16; o > 0; o >>= 1) s += __shfl_xor_sync(0xffffffffu, s, o);
    if (lane == 0) out[gw] = s + hb[0];
}

// ---------------- launch -----------------------------------------------------
extern "C" void kernel_launch(void* const* d_in, const int* in_sizes, int n_in,
                              void* d_out, int out_size) {
    const float* x    = (const float*)d_in[0];
    const int*   nt   = (const int*)  d_in[1];
    const int*   ei   = (const int*)  d_in[2];
    const float* wr   = (const float*)d_in[3];
    const float* wn   = (const float*)d_in[4];
    const float* bs   = (const float*)d_in[5];
    const float* lg   = (const float*)d_in[6];
    const float* lb   = (const float*)d_in[7];
    const float* hw   = (const float*)d_in[8];
    const float* hb   = (const float*)d_in[9];
    const int*   minT = (const int*)  d_in[10];
    const int*   up   = (const int*)  d_in[12];

    int n  = in_sizes[0] / C;
    int E_ = in_sizes[2] / 2;
    int n4 = PP * n;

    k_zero  <<<(n4 + 255) / 256, 256>>>(n4);
    k_copy_x<<<(n * (C / 4) + 255) / 256, 256>>>((const float4*)x, n * (C / 4));
    k_edge  <<<(E_ + 255) / 256, 256>>>(ei, nt, minT, up, E_, n);

    int nb = (n4 + 1023) / 1024;
    k_scan1<<<nb, 256>>>(n4);
    k_scan2<<<1, 1024>>>(nb);
    k_scan3<<<(n4 + 255) / 256, 256>>>(n4, E_);

    k_scatter<<<(E_ + 255) / 256, 256>>>(ei, E_, n);
    k_compact<<<(n4 + 255) / 256, 256>>>(n, n4);

    int gatherBlocks = (n * 32 + 255) / 256;
    int gemmBlocks   = (n + 127) / 128;
    for (int p = 0; p < PP; p++) {
        k_gather<<<gatherBlocks, 256>>>(p, n, 0);
        k_gemm  <<<gemmBlocks, 256>>>(wr, wn, bs, lg, lb, p, n, 0);
        k_gather<<<gatherBlocks, 256>>>(p, n, 1);
        k_gemm  <<<gemmBlocks, 256>>>(wr, wn, bs, lg, lb, p, n, 1);
    }

    k_head<<<(out_size * 32 + 255) / 256, 256>>>(hw, hb, (float*)d_out, out_size);
}